// round 2
// baseline (speedup 1.0000x reference)
#include <cuda_runtime.h>
#include <math.h>
#include <stdint.h>

#define NN     50000
#define NE     800000
#define EF     16
#define HID    64
#define NC     10
#define NPICK  4096

// ---------------- scratch (static device globals; no allocation) ----------------
__device__ float g_ew[4 * NE];        // per-layer edge gate scalars
__device__ float g_h[NN * HID];       // h = x @ convW[l]
__device__ float g_xa[NN * HID];      // ping
__device__ float g_xb[NN * HID];      // pong
__device__ float g_dis[NN];           // deg^-1/2 per layer
__device__ int   g_cnt[NN];
__device__ int   g_rowptr[NN + 1];
__device__ int   g_pos[NN];
__device__ int2  g_se[NE];            // (src node, edge id) sorted by dst

__device__ __forceinline__ int clampi(int v, int hi) {
    return v < 0 ? 0 : (v >= hi ? hi - 1 : v);
}

// ---------------- fused edge encoder + 4x gating MLP ----------------
__global__ __launch_bounds__(256) void k_edge(
    const float* __restrict__ eattr,
    const float* __restrict__ encW1, const float* __restrict__ encb1,
    const float* __restrict__ encW2, const float* __restrict__ encb2,
    const float* __restrict__ mlpW1, const float* __restrict__ mlpb1,
    const float* __restrict__ mlpW2, const float* __restrict__ mlpb2)
{
    __shared__ __align__(16) float sW1[EF * EF];
    __shared__ float sb1[EF];
    __shared__ __align__(16) float sW2[EF * EF];
    __shared__ float sb2[EF];
    __shared__ __align__(16) float sM1[4 * EF * HID];
    __shared__ float sMb1[4 * HID];
    __shared__ float sM2[4 * HID];
    __shared__ float sMb2[4];

    int tid = threadIdx.x;
    for (int i = tid; i < EF * EF; i += 256) { sW1[i] = encW1[i]; sW2[i] = encW2[i]; }
    if (tid < EF) { sb1[tid] = encb1[tid]; sb2[tid] = encb2[tid]; }
    for (int i = tid; i < 4 * EF * HID; i += 256) sM1[i] = mlpW1[i];
    for (int i = tid; i < 4 * HID; i += 256) { sMb1[i] = mlpb1[i]; sM2[i] = mlpW2[i]; }
    if (tid < 4) sMb2[tid] = mlpb2[tid];
    __syncthreads();

    int e = blockIdx.x * 256 + tid;
    if (e >= NE) return;

    // load edge_attr row
    float a[EF];
    const float4* a4 = (const float4*)(eattr + (size_t)e * EF);
    #pragma unroll
    for (int i = 0; i < 4; i++) {
        float4 v = a4[i];
        a[4*i] = v.x; a[4*i+1] = v.y; a[4*i+2] = v.z; a[4*i+3] = v.w;
    }

    // encoder layer 1
    float t[EF];
    #pragma unroll
    for (int j = 0; j < EF; j++) t[j] = sb1[j];
    #pragma unroll
    for (int k = 0; k < EF; k++) {
        float ak = a[k];
        const float4* w = (const float4*)&sW1[k * EF];
        #pragma unroll
        for (int j = 0; j < 4; j++) {
            float4 v = w[j];
            t[4*j] += ak * v.x; t[4*j+1] += ak * v.y; t[4*j+2] += ak * v.z; t[4*j+3] += ak * v.w;
        }
    }
    // encoder layer 2
    float ea[EF];
    #pragma unroll
    for (int j = 0; j < EF; j++) ea[j] = sb2[j];
    #pragma unroll
    for (int k = 0; k < EF; k++) {
        float ak = t[k];
        const float4* w = (const float4*)&sW2[k * EF];
        #pragma unroll
        for (int j = 0; j < 4; j++) {
            float4 v = w[j];
            ea[4*j] += ak * v.x; ea[4*j+1] += ak * v.y; ea[4*j+2] += ak * v.z; ea[4*j+3] += ak * v.w;
        }
    }

    // 4 gating MLPs (runtime loop to keep code in I-cache)
    #pragma unroll 1
    for (int l = 0; l < 4; l++) {
        float hv[HID];
        #pragma unroll
        for (int j = 0; j < HID; j++) hv[j] = sMb1[l * HID + j];
        #pragma unroll
        for (int k = 0; k < EF; k++) {
            float ek = ea[k];
            const float4* w = (const float4*)&sM1[(l * EF + k) * HID];
            #pragma unroll
            for (int j = 0; j < 16; j++) {
                float4 v = w[j];
                hv[4*j] += ek * v.x; hv[4*j+1] += ek * v.y; hv[4*j+2] += ek * v.z; hv[4*j+3] += ek * v.w;
            }
        }
        float z = sMb2[l];
        #pragma unroll
        for (int j = 0; j < HID; j++) z += fmaxf(hv[j], 0.f) * sM2[l * HID + j];
        g_ew[(size_t)l * NE + e] = 1.f / (1.f + __expf(-z));
    }
}

// ---------------- CSR build ----------------
__global__ void k_zero() {
    int i = blockIdx.x * blockDim.x + threadIdx.x;
    if (i < NN) g_cnt[i] = 0;
}

__global__ void k_count(const int* __restrict__ colp) {
    int e = blockIdx.x * blockDim.x + threadIdx.x;
    if (e < NE) atomicAdd(&g_cnt[clampi(colp[e], NN)], 1);
}

__global__ void k_scan() {
    __shared__ int ssum[1024];
    const int CH = (NN + 1023) / 1024;   // 49
    int t = threadIdx.x;
    int base = t * CH;
    int s = 0;
    for (int i = 0; i < CH; i++)
        if (base + i < NN) s += g_cnt[base + i];
    ssum[t] = s;
    __syncthreads();
    // inclusive Hillis-Steele scan
    for (int off = 1; off < 1024; off <<= 1) {
        int v = (t >= off) ? ssum[t - off] : 0;
        __syncthreads();
        ssum[t] += v;
        __syncthreads();
    }
    int run = ssum[t] - s;   // exclusive prefix
    for (int i = 0; i < CH; i++) {
        if (base + i < NN) {
            g_rowptr[base + i] = run;
            g_pos[base + i] = run;
            run += g_cnt[base + i];
        }
    }
    if (t == 0) g_rowptr[NN] = NE;
}

__global__ void k_scatter(const int* __restrict__ rowp,
                          const int* __restrict__ colp) {
    int e = blockIdx.x * blockDim.x + threadIdx.x;
    if (e >= NE) return;
    int c = clampi(colp[e], NN);
    int p = atomicAdd(&g_pos[c], 1);
    g_se[clampi(p, NE)] = make_int2(clampi(rowp[e], NN), e);
}

// ---------------- per-layer: dis = rsqrt(1 + sum ew) ----------------
__global__ __launch_bounds__(256) void k_dis(const float* __restrict__ ewl) {
    int w = (blockIdx.x * blockDim.x + threadIdx.x) >> 5;
    int lane = threadIdx.x & 31;
    if (w >= NN) return;
    int rs = g_rowptr[w], re = g_rowptr[w + 1];
    float s = 0.f;
    for (int p = rs + lane; p < re; p += 32) s += ewl[g_se[p].y];
    #pragma unroll
    for (int o = 16; o; o >>= 1) s += __shfl_xor_sync(0xffffffffu, s, o);
    if (lane == 0) g_dis[w] = rsqrtf(s + 1.f);   // +1 = self loop
}

// ---------------- h = x @ W (64x64), warp per row ----------------
__global__ __launch_bounds__(256) void k_gemm(const float* __restrict__ xin,
                                              const float* __restrict__ W) {
    __shared__ __align__(16) float sW[HID * HID];
    for (int i = threadIdx.x; i < HID * HID; i += 256) sW[i] = W[i];
    __syncthreads();
    int w = (blockIdx.x * 256 + threadIdx.x) >> 5;
    int lane = threadIdx.x & 31;
    if (w >= NN) return;
    float2 xv = *(const float2*)&xin[(size_t)w * HID + lane * 2];
    float ax = 0.f, ay = 0.f;
    #pragma unroll
    for (int k = 0; k < HID; k++) {
        float xk = __shfl_sync(0xffffffffu, (k & 1) ? xv.y : xv.x, k >> 1);
        float2 wv = *(const float2*)&sW[k * HID + lane * 2];
        ax += xk * wv.x; ay += xk * wv.y;
    }
    float2 o = make_float2(ax, ay);
    *(float2*)&g_h[(size_t)w * HID + lane * 2] = o;
}

// ---------------- SpMM: out[c] = sum norm * h[src] + dis^2 h[c] + b ----------------
__global__ __launch_bounds__(256) void k_spmm(const float* __restrict__ ewl,
                                              const float* __restrict__ bias,
                                              float* __restrict__ xout,
                                              int dorelu) {
    int c = (blockIdx.x * blockDim.x + threadIdx.x) >> 5;
    int lane = threadIdx.x & 31;
    if (c >= NN) return;
    int rs = g_rowptr[c], re = g_rowptr[c + 1];
    float disc = g_dis[c];
    float ax = 0.f, ay = 0.f;
    for (int p = rs; p < re; p++) {
        int2 se = g_se[p];
        float norm = disc * ewl[se.y] * g_dis[se.x];
        float2 hv = *(const float2*)&g_h[(size_t)se.x * HID + lane * 2];
        ax += norm * hv.x;
        ay += norm * hv.y;
    }
    float2 hc = *(const float2*)&g_h[(size_t)c * HID + lane * 2];
    float ns = disc * disc;
    ax += ns * hc.x; ay += ns * hc.y;
    float2 b = *(const float2*)&bias[lane * 2];
    ax += b.x; ay += b.y;
    if (dorelu) { ax = fmaxf(ax, 0.f); ay = fmaxf(ay, 0.f); }
    float2 o = make_float2(ax, ay);
    *(float2*)&xout[(size_t)c * HID + lane * 2] = o;
}

// ---------------- classifier + softmax at picked nodes ----------------
__global__ __launch_bounds__(128) void k_final(const float* __restrict__ xin,
                                               const float* __restrict__ linW,
                                               const float* __restrict__ linb,
                                               const int* __restrict__ pick,
                                               float* __restrict__ out) {
    __shared__ float sW[HID * NC];
    __shared__ float sb[NC];
    for (int i = threadIdx.x; i < HID * NC; i += 128) sW[i] = linW[i];
    if (threadIdx.x < NC) sb[threadIdx.x] = linb[threadIdx.x];
    __syncthreads();
    int t = blockIdx.x * 128 + threadIdx.x;
    if (t >= NPICK) return;
    int node = clampi(pick[t], NN);
    float lg[NC];
    #pragma unroll
    for (int j = 0; j < NC; j++) lg[j] = sb[j];
    const float4* xr = (const float4*)&xin[(size_t)node * HID];
    #pragma unroll
    for (int k4 = 0; k4 < 16; k4++) {
        float4 v = xr[k4];
        float xs[4] = {v.x, v.y, v.z, v.w};
        #pragma unroll
        for (int q = 0; q < 4; q++) {
            float xk = xs[q];
            #pragma unroll
            for (int j = 0; j < NC; j++) lg[j] += xk * sW[(k4 * 4 + q) * NC + j];
        }
    }
    float m = lg[0];
    #pragma unroll
    for (int j = 1; j < NC; j++) m = fmaxf(m, lg[j]);
    float ex[NC];
    float s = 0.f;
    #pragma unroll
    for (int j = 0; j < NC; j++) { ex[j] = __expf(lg[j] - m); s += ex[j]; }
    float inv = 1.f / s;
    #pragma unroll
    for (int j = 0; j < NC; j++) out[(size_t)t * NC + j] = ex[j] * inv;
}

// ---------------- launch ----------------
extern "C" void kernel_launch(void* const* d_in, const int* in_sizes, int n_in,
                              void* d_out, int out_size) {
    const float* x      = (const float*)d_in[0];
    const float* eattr  = (const float*)d_in[1];
    const float* encW1  = (const float*)d_in[2];
    const float* encb1  = (const float*)d_in[3];
    const float* encW2  = (const float*)d_in[4];
    const float* encb2  = (const float*)d_in[5];
    const float* convW  = (const float*)d_in[6];
    const float* convB  = (const float*)d_in[7];
    const float* mlpW1  = (const float*)d_in[8];
    const float* mlpb1  = (const float*)d_in[9];
    const float* mlpW2  = (const float*)d_in[10];
    const float* mlpb2  = (const float*)d_in[11];
    const float* linW   = (const float*)d_in[12];
    const float* linb   = (const float*)d_in[13];
    const int* eidx     = (const int*)d_in[14];   // JAX x64 disabled -> int32
    const int* pick     = (const int*)d_in[15];   // int32
    float* out = (float*)d_out;

    const int* rowp = eidx;
    const int* colp = eidx + NE;

    float *ew, *xa, *xb;
    cudaGetSymbolAddress((void**)&ew, g_ew);
    cudaGetSymbolAddress((void**)&xa, g_xa);
    cudaGetSymbolAddress((void**)&xb, g_xb);

    const int EB = (NE + 255) / 256;        // 3125 blocks, edge-parallel
    const int WB = (NN * 32 + 255) / 256;   // 6250 blocks, warp-per-node

    // edge gates (layer-invariant input, all 4 layers at once)
    k_edge<<<EB, 256>>>(eattr, encW1, encb1, encW2, encb2, mlpW1, mlpb1, mlpW2, mlpb2);

    // CSR by destination
    k_zero<<<(NN + 255) / 256, 256>>>();
    k_count<<<EB, 256>>>(colp);
    k_scan<<<1, 1024>>>();
    k_scatter<<<EB, 256>>>(rowp, colp);

    const float* xin = x;
    float* bufs[2] = { xa, xb };
    for (int l = 0; l < 4; l++) {
        const float* ewl = ew + (size_t)l * NE;
        k_dis<<<WB, 256>>>(ewl);
        k_gemm<<<WB, 256>>>(xin, convW + l * HID * HID);
        k_spmm<<<WB, 256>>>(ewl, convB + l * HID, bufs[l & 1], (l < 3) ? 1 : 0);
        xin = bufs[l & 1];
    }

    k_final<<<32, 128>>>(xin, linW, linb, pick, out);
}